// round 1
// baseline (speedup 1.0000x reference)
#include <cuda_runtime.h>
#include <math.h>

// ---------------- problem constants ----------------
constexpr int B_ = 2, N_ = 2048, D_ = 768, H_ = 12, DH_ = 64, M_ = 266, FF_ = 3072;
constexpr int BND_  = B_ * N_ * D_;              // 3,145,728
constexpr int BHNM_ = B_ * H_ * N_ * M_;         // 13,074,432
constexpr int BNFF_ = B_ * N_ * FF_;             // 12,582,912
constexpr float DN_    = 0.35355339059327373f;   // 64^-0.25
constexpr float RATIO_ = 0.06131393283046181f;   // 266^-0.5
constexpr float EPS_KER_ = 1e-4f;
constexpr float EPS_DEN_ = 1e-6f;

// ---------------- scratch (device globals; no allocation allowed) -----------
__device__ float g_h [BND_];   // layernorm output (reused for h1 and h2)
__device__ float g_q [BND_];
__device__ float g_k [BND_];
__device__ float g_v [BND_];
__device__ float g_o [BND_];   // attention output, [B,N,H*DH]
__device__ float g_x2[BND_];   // x + attn projection
__device__ float g_qp[BHNM_];  // [B,H,N,M] query features
__device__ float g_kp[BHNM_];  // [B,H,N,M] key features (pass1: dd-diag, pass2: final)
__device__ float g_ff[BNFF_];  // [B,N,FF]
__device__ float g_kmax[1];

// ---------------- helpers ----------------
__device__ __forceinline__ void atomicMaxFloat(float* addr, float val) {
    int* ia = (int*)addr;
    int old = *ia;
    while (__int_as_float(old) < val) {
        int assumed = old;
        old = atomicCAS(ia, assumed, __float_as_int(val));
        if (old == assumed) break;
    }
}

__device__ __forceinline__ float gelu_exact(float v) {
    return 0.5f * v * (1.0f + erff(v * 0.70710678118654752f));
}

// ---------------- layernorm: one block per row ----------------
__global__ void ln_kernel(const float* __restrict__ x, const float* __restrict__ g,
                          const float* __restrict__ b, float* __restrict__ y) {
    __shared__ float red[256];
    const int row = blockIdx.x;
    const int tid = threadIdx.x;
    const float* xr = x + (size_t)row * D_;

    float s = 0.f;
    for (int i = tid; i < D_; i += 256) s += xr[i];
    red[tid] = s; __syncthreads();
    for (int o = 128; o > 0; o >>= 1) { if (tid < o) red[tid] += red[tid + o]; __syncthreads(); }
    const float mu = red[0] * (1.0f / D_);
    __syncthreads();

    float s2 = 0.f;
    for (int i = tid; i < D_; i += 256) { float d = xr[i] - mu; s2 += d * d; }
    red[tid] = s2; __syncthreads();
    for (int o = 128; o > 0; o >>= 1) { if (tid < o) red[tid] += red[tid + o]; __syncthreads(); }
    const float inv = rsqrtf(red[0] * (1.0f / D_) + 1e-5f);

    float* yr = y + (size_t)row * D_;
    for (int i = tid; i < D_; i += 256) yr[i] = (xr[i] - mu) * inv * g[i] + b[i];
}

// ---------------- generic tiled fp32 GEMM: C = act(A@Bm + bias) (+resid) ----
// A: [Md,Kd] row-major, Bm: [Kd,Nd] row-major. Md%64==0, Nd%64==0, Kd%16==0.
__global__ void gemm_kernel(const float* __restrict__ A, const float* __restrict__ Bm,
                            const float* __restrict__ bias, const float* __restrict__ resid,
                            float* __restrict__ C, int Md, int Nd, int Kd, int act) {
    __shared__ float As[16][64];
    __shared__ float Bs[16][64];
    const int tx = threadIdx.x & 15, ty = threadIdx.x >> 4;
    const int row0 = blockIdx.y * 64, col0 = blockIdx.x * 64;

    float acc[4][4];
#pragma unroll
    for (int u = 0; u < 4; u++)
#pragma unroll
        for (int w = 0; w < 4; w++) acc[u][w] = 0.f;

    for (int k0 = 0; k0 < Kd; k0 += 16) {
        for (int t = threadIdx.x; t < 64 * 16; t += 256) {
            int i = t >> 4, kk = t & 15;
            As[kk][i] = A[(size_t)(row0 + i) * Kd + k0 + kk];
        }
        for (int t = threadIdx.x; t < 16 * 64; t += 256) {
            int kk = t >> 6, j = t & 63;
            Bs[kk][j] = Bm[(size_t)(k0 + kk) * Nd + col0 + j];
        }
        __syncthreads();
#pragma unroll
        for (int kk = 0; kk < 16; kk++) {
            float a[4], bv[4];
#pragma unroll
            for (int u = 0; u < 4; u++) a[u]  = As[kk][ty * 4 + u];
#pragma unroll
            for (int u = 0; u < 4; u++) bv[u] = Bs[kk][tx * 4 + u];
#pragma unroll
            for (int u = 0; u < 4; u++)
#pragma unroll
                for (int w = 0; w < 4; w++) acc[u][w] += a[u] * bv[w];
        }
        __syncthreads();
    }

#pragma unroll
    for (int u = 0; u < 4; u++) {
        const int r = row0 + ty * 4 + u;
#pragma unroll
        for (int w = 0; w < 4; w++) {
            const int c = col0 + tx * 4 + w;
            float v = acc[u][w] + bias[c];
            if (act == 1) v = gelu_exact(v);
            if (resid) v += resid[(size_t)r * Nd + c];
            C[(size_t)r * Nd + c] = v;
        }
    }
}

// ---------------- FAVOR+ feature kernels ----------------
// ROWS rows of one (b,h) per block. proj staged in smem (padded stride 65).
constexpr int FROWS_ = 16;

__global__ void feat_kernel(const float* __restrict__ data,  // [B,N,D] head-interleaved
                            const float* __restrict__ proj,  // [M,DH]
                            float* __restrict__ outp,        // [B,H,N,M]
                            float* __restrict__ kmax, int is_query) {
    extern __shared__ float sm[];
    float* sproj = sm;                       // M_ * 65
    float* srow  = sproj + M_ * 65;          // FROWS_ * DH_
    float* sdd   = srow + FROWS_ * DH_;      // FROWS_ * M_
    __shared__ float sdiag[FROWS_];
    __shared__ float smx[FROWS_];
    __shared__ float red[256];

    const int b = blockIdx.z, h = blockIdx.y, n0 = blockIdx.x * FROWS_;
    const int tid = threadIdx.x;

    for (int i = tid; i < M_ * DH_; i += 256) {
        int m = i / DH_, d = i - m * DH_;
        sproj[m * 65 + d] = proj[i];
    }
    for (int i = tid; i < FROWS_ * DH_; i += 256) {
        int r = i >> 6, d = i & 63;
        srow[i] = data[((size_t)b * N_ + n0 + r) * D_ + h * DH_ + d];
    }
    __syncthreads();

    for (int i = tid; i < FROWS_ * M_; i += 256) {
        int r = i / M_, m = i - r * M_;
        const float* dp = srow + r * DH_;
        const float* pp = sproj + m * 65;
        float acc = 0.f;
#pragma unroll
        for (int d = 0; d < DH_; d++) acc += dp[d] * pp[d];
        sdd[i] = acc * DN_;
    }
    __syncthreads();

    if (tid < FROWS_) {
        const float* dp = srow + tid * DH_;
        float s = 0.f;
#pragma unroll
        for (int d = 0; d < DH_; d++) s += dp[d] * dp[d];
        sdiag[tid] = s * 0.5f * DN_ * DN_;
        if (is_query) {
            float mx = -3e38f;
            for (int m = 0; m < M_; m++) mx = fmaxf(mx, sdd[tid * M_ + m]);
            smx[tid] = mx;
        }
    }
    __syncthreads();

    const size_t obase = ((size_t)(b * H_ + h) * N_ + n0) * M_;
    if (is_query) {
        for (int i = tid; i < FROWS_ * M_; i += 256) {
            int r = i / M_, m = i - r * M_;
            outp[obase + (size_t)r * M_ + m] =
                RATIO_ * (expf(sdd[i] - sdiag[r] - smx[r]) + EPS_KER_);
        }
    } else {
        float lmax = -3e38f;
        for (int i = tid; i < FROWS_ * M_; i += 256) {
            int r = i / M_, m = i - r * M_;
            float v = sdd[i];
            lmax = fmaxf(lmax, v);                       // max over dd (pre-diag!)
            outp[obase + (size_t)r * M_ + m] = v - sdiag[r];
        }
        red[tid] = lmax; __syncthreads();
        for (int o = 128; o > 0; o >>= 1) { if (tid < o) red[tid] = fmaxf(red[tid], red[tid + o]); __syncthreads(); }
        if (tid == 0) atomicMaxFloat(kmax, red[0]);
    }
}

__global__ void kmax_init_kernel(float* kmax) { kmax[0] = -3e38f; }

__global__ void kexp_kernel(float* __restrict__ kp, const float* __restrict__ kmax) {
    int i = blockIdx.x * 256 + threadIdx.x;
    if (i < BHNM_) {
        float v = kp[i];
        kp[i] = RATIO_ * (expf(v - kmax[0]) + EPS_KER_);
    }
}

// ---------------- chunked causal linear attention scan ----------------
// One block per (b,h). State S[M,DH] + z[M] in smem, chunk C=32.
constexpr int CH_ = 32;
constexpr int QSTR_ = 267;  // padded feature stride

__global__ void scan_kernel(const float* __restrict__ qp,  // [B,H,N,M]
                            const float* __restrict__ kp,  // [B,H,N,M]
                            const float* __restrict__ v,   // [B,N,D] head-interleaved
                            float* __restrict__ o) {       // [B,N,D]
    extern __shared__ float sm[];
    float* S   = sm;                    // M_*DH_ (17024)
    float* z   = S + M_ * DH_;          // 268
    float* qc  = z + 268;               // CH_*QSTR_
    float* kc  = qc + CH_ * QSTR_;      // CH_*QSTR_
    float* vc  = kc + CH_ * QSTR_;      // CH_*DH_
    float* Am  = vc + CH_ * DH_;        // CH_*CH_
    float* den = Am + CH_ * CH_;        // CH_

    const int bh = blockIdx.x;
    const int b = bh / H_, h = bh - b * H_;
    const int tid = threadIdx.x;
    const size_t fbase = (size_t)bh * N_ * M_;

    for (int i = tid; i < M_ * DH_; i += 256) S[i] = 0.f;
    for (int i = tid; i < M_; i += 256) z[i] = 0.f;
    __syncthreads();

    for (int c = 0; c < N_ / CH_; c++) {
        const int n0 = c * CH_;
        // load chunk
        for (int i = tid; i < CH_ * M_; i += 256) {
            int r = i / M_, m = i - r * M_;
            size_t gi = fbase + (size_t)(n0 + r) * M_ + m;
            qc[r * QSTR_ + m] = qp[gi];
            kc[r * QSTR_ + m] = kp[gi];
        }
        for (int i = tid; i < CH_ * DH_; i += 256) {
            int r = i >> 6, e = i & 63;
            vc[i] = v[((size_t)b * N_ + n0 + r) * D_ + h * DH_ + e];
        }
        __syncthreads();

        // A[i][j] = q_i . k_j
        for (int idx = tid; idx < CH_ * CH_; idx += 256) {
            int i = idx >> 5, j = idx & 31;
            const float* qr = qc + i * QSTR_;
            const float* kr = kc + j * QSTR_;
            float acc = 0.f;
            for (int m = 0; m < M_; m++) acc += qr[m] * kr[m];
            Am[idx] = acc;
        }
        __syncthreads();

        // den[i] = q_i.z + eps*sum(q_i) + sum_{j<=i} A[i][j]
        if (tid < CH_) {
            const float* qr = qc + tid * QSTR_;
            float s = 0.f, qs = 0.f;
            for (int m = 0; m < M_; m++) { float qv = qr[m]; s += qv * z[m]; qs += qv; }
            float acc = s + EPS_DEN_ * qs;
            for (int j = 0; j <= tid; j++) acc += Am[tid * CH_ + j];
            den[tid] = acc;
        }
        __syncthreads();

        // out[i][e] = (q_i^T S + sum_{j<=i} A[i][j] v_j[e]) / den[i]
        for (int idx = tid; idx < CH_ * DH_; idx += 256) {
            int i = idx >> 6, e = idx & 63;
            const float* qr = qc + i * QSTR_;
            float acc = 0.f;
            for (int m = 0; m < M_; m++) acc += qr[m] * S[m * DH_ + e];
            for (int j = 0; j <= i; j++) acc += Am[i * CH_ + j] * vc[j * DH_ + e];
            o[((size_t)b * N_ + n0 + i) * D_ + h * DH_ + e] = acc / den[i];
        }
        __syncthreads();

        // state update: S += kc^T vc ; z += sum kc
        for (int idx = tid; idx < M_ * DH_; idx += 256) {
            int m = idx >> 6, e = idx & 63;
            float acc = S[idx];
            for (int j = 0; j < CH_; j++) acc += kc[j * QSTR_ + m] * vc[j * DH_ + e];
            S[idx] = acc;
        }
        for (int m = tid; m < M_; m += 256) {
            float s = z[m];
            for (int j = 0; j < CH_; j++) s += kc[j * QSTR_ + m];
            z[m] = s;
        }
        __syncthreads();
    }
}

// ---------------- host launcher ----------------
extern "C" void kernel_launch(void* const* d_in, const int* in_sizes, int n_in,
                              void* d_out, int out_size) {
    const float* x     = (const float*)d_in[0];
    const float* ln1_g = (const float*)d_in[1];
    const float* ln1_b = (const float*)d_in[2];
    const float* Wq    = (const float*)d_in[3];
    const float* bq    = (const float*)d_in[4];
    const float* Wk    = (const float*)d_in[5];
    const float* bk    = (const float*)d_in[6];
    const float* Wv    = (const float*)d_in[7];
    const float* bv    = (const float*)d_in[8];
    const float* Wo    = (const float*)d_in[9];
    const float* bo    = (const float*)d_in[10];
    const float* proj  = (const float*)d_in[11];
    const float* ln2_g = (const float*)d_in[12];
    const float* ln2_b = (const float*)d_in[13];
    const float* W1    = (const float*)d_in[14];
    const float* b1    = (const float*)d_in[15];
    const float* W2    = (const float*)d_in[16];
    const float* b2    = (const float*)d_in[17];
    float* out = (float*)d_out;

    float *p_h, *p_q, *p_k, *p_v, *p_o, *p_x2, *p_qp, *p_kp, *p_ff, *p_kmax;
    cudaGetSymbolAddress((void**)&p_h, g_h);
    cudaGetSymbolAddress((void**)&p_q, g_q);
    cudaGetSymbolAddress((void**)&p_k, g_k);
    cudaGetSymbolAddress((void**)&p_v, g_v);
    cudaGetSymbolAddress((void**)&p_o, g_o);
    cudaGetSymbolAddress((void**)&p_x2, g_x2);
    cudaGetSymbolAddress((void**)&p_qp, g_qp);
    cudaGetSymbolAddress((void**)&p_kp, g_kp);
    cudaGetSymbolAddress((void**)&p_ff, g_ff);
    cudaGetSymbolAddress((void**)&p_kmax, g_kmax);

    const int feat_smem = (M_ * 65 + FROWS_ * DH_ + FROWS_ * M_) * 4;
    const int scan_smem = (M_ * DH_ + 268 + 2 * CH_ * QSTR_ + CH_ * DH_ + CH_ * CH_ + CH_) * 4;
    cudaFuncSetAttribute(feat_kernel, cudaFuncAttributeMaxDynamicSharedMemorySize, feat_smem);
    cudaFuncSetAttribute(scan_kernel, cudaFuncAttributeMaxDynamicSharedMemorySize, scan_smem);

    const int MR = B_ * N_;  // 4096 rows

    // 1. LN1
    ln_kernel<<<MR, 256>>>(x, ln1_g, ln1_b, p_h);

    // 2. QKV projections
    gemm_kernel<<<dim3(D_ / 64, MR / 64), 256>>>(p_h, Wq, bq, nullptr, p_q, MR, D_, D_, 0);
    gemm_kernel<<<dim3(D_ / 64, MR / 64), 256>>>(p_h, Wk, bk, nullptr, p_k, MR, D_, D_, 0);
    gemm_kernel<<<dim3(D_ / 64, MR / 64), 256>>>(p_h, Wv, bv, nullptr, p_v, MR, D_, D_, 0);

    // 3. feature maps
    dim3 fgrid(N_ / FROWS_, H_, B_);
    feat_kernel<<<fgrid, 256, feat_smem>>>(p_q, proj, p_qp, nullptr, 1);
    kmax_init_kernel<<<1, 1>>>(p_kmax);
    feat_kernel<<<fgrid, 256, feat_smem>>>(p_k, proj, p_kp, p_kmax, 0);
    kexp_kernel<<<(BHNM_ + 255) / 256, 256>>>(p_kp, p_kmax);

    // 4. causal linear attention scan
    scan_kernel<<<B_ * H_, 256, scan_smem>>>(p_qp, p_kp, p_v, p_o);

    // 5. output projection + residual
    gemm_kernel<<<dim3(D_ / 64, MR / 64), 256>>>(p_o, Wo, bo, x, p_x2, MR, D_, D_, 0);

    // 6. LN2 + MLP
    ln_kernel<<<MR, 256>>>(p_x2, ln2_g, ln2_b, p_h);
    gemm_kernel<<<dim3(FF_ / 64, MR / 64), 256>>>(p_h, W1, b1, nullptr, p_ff, MR, FF_, D_, 1);
    gemm_kernel<<<dim3(D_ / 64, MR / 64), 256>>>(p_ff, W2, b2, p_x2, out, MR, D_, FF_, 0);
}

// round 2
// speedup vs baseline: 3.5502x; 3.5502x over previous
#include <cuda_runtime.h>
#include <math.h>

// ---------------- problem constants ----------------
constexpr int B_ = 2, N_ = 2048, D_ = 768, H_ = 12, DH_ = 64, M_ = 266, FF_ = 3072;
constexpr int BND_  = B_ * N_ * D_;
constexpr int BHNM_ = B_ * H_ * N_ * M_;
constexpr int BNFF_ = B_ * N_ * FF_;
constexpr float DN_    = 0.35355339059327373f;   // 64^-0.25
constexpr float RATIO_ = 0.06131393283046181f;   // 266^-0.5
constexpr float EPS_KER_ = 1e-4f;
constexpr float EPS_DEN_ = 1e-6f;

constexpr int SC_ = 64;          // scan chunk
constexpr int NC_ = N_ / SC_;    // 32 chunks
constexpr int BH_ = B_ * H_;     // 24
constexpr int KSTR_ = 273;       // padded feature stride (odd -> conflict-free)

// ---------------- scratch (device globals; no allocation allowed) -----------
__device__ float g_h [BND_];
__device__ float g_q [BND_];
__device__ float g_k [BND_];
__device__ float g_v [BND_];
__device__ float g_o [BND_];
__device__ float g_x2[BND_];
__device__ float g_qp[BHNM_];
__device__ float g_kp[BHNM_];
__device__ float g_ff[BNFF_];
__device__ float g_Sc[(size_t)BH_ * NC_ * (M_ * DH_)];   // per-chunk K^T V states
__device__ float g_zc[(size_t)BH_ * NC_ * M_];           // per-chunk k sums
__device__ float g_kmax[1];

// ---------------- helpers ----------------
__device__ __forceinline__ void atomicMaxFloat(float* addr, float val) {
    int* ia = (int*)addr;
    int old = *ia;
    while (__int_as_float(old) < val) {
        int assumed = old;
        old = atomicCAS(ia, assumed, __float_as_int(val));
        if (old == assumed) break;
    }
}

__device__ __forceinline__ float gelu_exact(float v) {
    return 0.5f * v * (1.0f + erff(v * 0.70710678118654752f));
}

__device__ __forceinline__ unsigned f2tf32(float f) {
    unsigned u;
    asm("cvt.rna.tf32.f32 %0, %1;" : "=r"(u) : "f"(f));
    return u;
}

// ---------------- layernorm: one block per row ----------------
__global__ void ln_kernel(const float* __restrict__ x, const float* __restrict__ g,
                          const float* __restrict__ b, float* __restrict__ y) {
    __shared__ float red[256];
    const int row = blockIdx.x;
    const int tid = threadIdx.x;
    const float* xr = x + (size_t)row * D_;

    float s = 0.f;
    for (int i = tid; i < D_; i += 256) s += xr[i];
    red[tid] = s; __syncthreads();
    for (int o = 128; o > 0; o >>= 1) { if (tid < o) red[tid] += red[tid + o]; __syncthreads(); }
    const float mu = red[0] * (1.0f / D_);
    __syncthreads();

    float s2 = 0.f;
    for (int i = tid; i < D_; i += 256) { float d = xr[i] - mu; s2 += d * d; }
    red[tid] = s2; __syncthreads();
    for (int o = 128; o > 0; o >>= 1) { if (tid < o) red[tid] += red[tid + o]; __syncthreads(); }
    const float inv = rsqrtf(red[0] * (1.0f / D_) + 1e-5f);

    float* yr = y + (size_t)row * D_;
    for (int i = tid; i < D_; i += 256) yr[i] = (xr[i] - mu) * inv * g[i] + b[i];
}

// ---------------- tf32 tensor-core GEMM ----------------
// C[Md,Nd] = act(A[Md,Kd] @ Bm[Kd,Nd] + bias) (+ resid). Md%128==0, Nd%128==0, Kd%32==0.
constexpr int AS_STR = 36;   // 32 + 4 pad
constexpr int BS_STR = 136;  // 128 + 8 pad

__global__ __launch_bounds__(256)
void gemm_tc_kernel(const float* __restrict__ A, const float* __restrict__ Bm,
                    const float* __restrict__ bias, const float* __restrict__ resid,
                    float* __restrict__ C, int Md, int Nd, int Kd, int act) {
    __shared__ unsigned As[128 * AS_STR];
    __shared__ unsigned Bs[32 * BS_STR];

    const int tid = threadIdx.x;
    const int lane = tid & 31, warp = tid >> 5;
    const int warp_m = warp >> 2;      // 0..1 -> 64-row half
    const int warp_n = warp & 3;       // 0..3 -> 32-col slice
    const int g = lane >> 2, tg = lane & 3;
    const int row0 = blockIdx.y * 128, col0 = blockIdx.x * 128;

    float c[4][4][4];
#pragma unroll
    for (int mt = 0; mt < 4; mt++)
#pragma unroll
        for (int nt = 0; nt < 4; nt++)
#pragma unroll
            for (int u = 0; u < 4; u++) c[mt][nt][u] = 0.f;

    for (int k0 = 0; k0 < Kd; k0 += 32) {
        // A tile: 128x32, float4 loads, cvt to tf32
        for (int c4 = tid; c4 < 1024; c4 += 256) {
            int r = c4 >> 3, cc = (c4 & 7) * 4;
            const float4 v = *(const float4*)&A[(size_t)(row0 + r) * Kd + k0 + cc];
            unsigned* dst = &As[r * AS_STR + cc];
            dst[0] = f2tf32(v.x); dst[1] = f2tf32(v.y);
            dst[2] = f2tf32(v.z); dst[3] = f2tf32(v.w);
        }
        // B tile: 32x128
        for (int c4 = tid; c4 < 1024; c4 += 256) {
            int r = c4 >> 5, cc = (c4 & 31) * 4;
            const float4 v = *(const float4*)&Bm[(size_t)(k0 + r) * Nd + col0 + cc];
            unsigned* dst = &Bs[r * BS_STR + cc];
            dst[0] = f2tf32(v.x); dst[1] = f2tf32(v.y);
            dst[2] = f2tf32(v.z); dst[3] = f2tf32(v.w);
        }
        __syncthreads();

#pragma unroll
        for (int k8 = 0; k8 < 4; k8++) {
            const int kk = k8 * 8;
            unsigned af[4][4], bf[4][2];
#pragma unroll
            for (int mt = 0; mt < 4; mt++) {
                const int rb = warp_m * 64 + mt * 16;
                af[mt][0] = As[(rb + g)     * AS_STR + kk + tg];
                af[mt][1] = As[(rb + g + 8) * AS_STR + kk + tg];
                af[mt][2] = As[(rb + g)     * AS_STR + kk + tg + 4];
                af[mt][3] = As[(rb + g + 8) * AS_STR + kk + tg + 4];
            }
#pragma unroll
            for (int nt = 0; nt < 4; nt++) {
                const int cb = warp_n * 32 + nt * 8 + g;
                bf[nt][0] = Bs[(kk + tg)     * BS_STR + cb];
                bf[nt][1] = Bs[(kk + tg + 4) * BS_STR + cb];
            }
#pragma unroll
            for (int mt = 0; mt < 4; mt++)
#pragma unroll
                for (int nt = 0; nt < 4; nt++) {
                    asm volatile(
                        "mma.sync.aligned.m16n8k8.row.col.f32.tf32.tf32.f32 "
                        "{%0,%1,%2,%3}, {%4,%5,%6,%7}, {%8,%9}, {%0,%1,%2,%3};"
                        : "+f"(c[mt][nt][0]), "+f"(c[mt][nt][1]),
                          "+f"(c[mt][nt][2]), "+f"(c[mt][nt][3])
                        : "r"(af[mt][0]), "r"(af[mt][1]), "r"(af[mt][2]), "r"(af[mt][3]),
                          "r"(bf[nt][0]), "r"(bf[nt][1]));
                }
        }
        __syncthreads();
    }

    // epilogue
#pragma unroll
    for (int mt = 0; mt < 4; mt++) {
        const int r1 = row0 + warp_m * 64 + mt * 16 + g;
        const int r2 = r1 + 8;
#pragma unroll
        for (int nt = 0; nt < 4; nt++) {
            const int cc = col0 + warp_n * 32 + nt * 8 + 2 * tg;
            const float b0 = bias[cc], b1 = bias[cc + 1];
            float v00 = c[mt][nt][0] + b0, v01 = c[mt][nt][1] + b1;
            float v10 = c[mt][nt][2] + b0, v11 = c[mt][nt][3] + b1;
            if (act == 1) {
                v00 = gelu_exact(v00); v01 = gelu_exact(v01);
                v10 = gelu_exact(v10); v11 = gelu_exact(v11);
            }
            if (resid) {
                const float2 q0 = *(const float2*)&resid[(size_t)r1 * Nd + cc];
                const float2 q1 = *(const float2*)&resid[(size_t)r2 * Nd + cc];
                v00 += q0.x; v01 += q0.y; v10 += q1.x; v11 += q1.y;
            }
            *(float2*)&C[(size_t)r1 * Nd + cc] = make_float2(v00, v01);
            *(float2*)&C[(size_t)r2 * Nd + cc] = make_float2(v10, v11);
        }
    }
}

// ---------------- FAVOR+ feature kernels ----------------
constexpr int FROWS_ = 16;

__global__ void feat_kernel(const float* __restrict__ data,  // [B,N,D] head-interleaved
                            const float* __restrict__ proj,  // [M,DH]
                            float* __restrict__ outp,        // [B,H,N,M]
                            float* __restrict__ kmax, int is_query) {
    extern __shared__ float sm[];
    float* sproj = sm;                       // M_ * 65
    float* srow  = sproj + M_ * 65;          // FROWS_ * DH_
    float* sdd   = srow + FROWS_ * DH_;      // FROWS_ * M_
    __shared__ float sdiag[FROWS_];
    __shared__ float smx[FROWS_];
    __shared__ float red[256];

    const int b = blockIdx.z, h = blockIdx.y, n0 = blockIdx.x * FROWS_;
    const int tid = threadIdx.x;

    for (int i = tid; i < M_ * DH_; i += 256) {
        int m = i / DH_, d = i - m * DH_;
        sproj[m * 65 + d] = proj[i];
    }
    for (int i = tid; i < FROWS_ * DH_; i += 256) {
        int r = i >> 6, d = i & 63;
        srow[i] = data[((size_t)b * N_ + n0 + r) * D_ + h * DH_ + d];
    }
    __syncthreads();

    for (int i = tid; i < FROWS_ * M_; i += 256) {
        int r = i / M_, m = i - r * M_;
        const float* dp = srow + r * DH_;
        const float* pp = sproj + m * 65;
        float acc = 0.f;
#pragma unroll
        for (int d = 0; d < DH_; d++) acc += dp[d] * pp[d];
        sdd[i] = acc * DN_;
    }
    __syncthreads();

    if (tid < FROWS_) {
        const float* dp = srow + tid * DH_;
        float s = 0.f;
#pragma unroll
        for (int d = 0; d < DH_; d++) s += dp[d] * dp[d];
        sdiag[tid] = s * 0.5f * DN_ * DN_;
        if (is_query) {
            float mx = -3e38f;
            for (int m = 0; m < M_; m++) mx = fmaxf(mx, sdd[tid * M_ + m]);
            smx[tid] = mx;
        }
    }
    __syncthreads();

    const size_t obase = ((size_t)(b * H_ + h) * N_ + n0) * M_;
    if (is_query) {
        for (int i = tid; i < FROWS_ * M_; i += 256) {
            int r = i / M_, m = i - r * M_;
            outp[obase + (size_t)r * M_ + m] =
                RATIO_ * (expf(sdd[i] - sdiag[r] - smx[r]) + EPS_KER_);
        }
    } else {
        float lmax = -3e38f;
        for (int i = tid; i < FROWS_ * M_; i += 256) {
            int r = i / M_, m = i - r * M_;
            float v = sdd[i];
            lmax = fmaxf(lmax, v);
            outp[obase + (size_t)r * M_ + m] = v - sdiag[r];
        }
        red[tid] = lmax; __syncthreads();
        for (int o = 128; o > 0; o >>= 1) { if (tid < o) red[tid] = fmaxf(red[tid], red[tid + o]); __syncthreads(); }
        if (tid == 0) atomicMaxFloat(kmax, red[0]);
    }
}

__global__ void kmax_init_kernel(float* kmax) { kmax[0] = -3e38f; }

__global__ void kexp_kernel(float* __restrict__ kp, const float* __restrict__ kmax) {
    int i = blockIdx.x * 256 + threadIdx.x;
    if (i < BHNM_) {
        float v = kp[i];
        kp[i] = RATIO_ * (expf(v - kmax[0]) + EPS_KER_);
    }
}

// ---------------- causal linear attention: 3-pass parallel scan ----------------
// Pass A: per (bh, chunk): local S_c = K_c^T V_c  [M,DH], z_c = sum_j k_j  [M]
__global__ void passA_kernel(const float* __restrict__ kp, const float* __restrict__ v,
                             float* __restrict__ Sc, float* __restrict__ zc) {
    extern __shared__ float sm[];
    float* kc = sm;                   // SC_*KSTR_
    float* vc = kc + SC_ * KSTR_;     // SC_*DH_
    const int bh = blockIdx.y, c = blockIdx.x;
    const int b = bh / H_, h = bh - b * H_;
    const int n0 = c * SC_;
    const int tid = threadIdx.x;
    const size_t fbase = (size_t)bh * N_ * M_;

    for (int i = tid; i < SC_ * KSTR_; i += 256) {
        int r = i / KSTR_, m = i - r * KSTR_;
        kc[i] = (m < M_) ? kp[fbase + (size_t)(n0 + r) * M_ + m] : 0.f;
    }
    for (int i = tid; i < SC_ * DH_; i += 256) {
        int r = i >> 6, e = i & 63;
        vc[i] = v[((size_t)b * N_ + n0 + r) * D_ + h * DH_ + e];
    }
    __syncthreads();

    const int e = tid & 63;
    const int mg = tid >> 6;   // 0..3
    float* out = Sc + ((size_t)bh * NC_ + c) * (M_ * DH_);
    for (int m0 = mg * 8; m0 < 272; m0 += 32) {
        float acc[8] = {0.f, 0.f, 0.f, 0.f, 0.f, 0.f, 0.f, 0.f};
        for (int j = 0; j < SC_; j++) {
            const float vv = vc[j * DH_ + e];
#pragma unroll
            for (int t = 0; t < 8; t++) acc[t] += kc[j * KSTR_ + m0 + t] * vv;
        }
#pragma unroll
        for (int t = 0; t < 8; t++)
            if (m0 + t < M_) out[(m0 + t) * DH_ + e] = acc[t];
    }
    for (int m = tid; m < M_; m += 256) {
        float s = 0.f;
        for (int j = 0; j < SC_; j++) s += kc[j * KSTR_ + m];
        zc[((size_t)bh * NC_ + c) * M_ + m] = s;
    }
}

// Pass B: in-place exclusive prefix over chunks (per bh, per element)
__global__ void passB_kernel(float* __restrict__ Sc, float* __restrict__ zc) {
    const int bh = blockIdx.x;
    const int i = blockIdx.y * 256 + threadIdx.x;
    if (i < M_ * DH_) {
        float run = 0.f;
        const size_t base = (size_t)bh * NC_ * (M_ * DH_) + i;
        for (int c = 0; c < NC_; c++) {
            float* p = Sc + base + (size_t)c * (M_ * DH_);
            const float t = *p; *p = run; run += t;
        }
    } else {
        const int m = i - M_ * DH_;
        if (m < M_) {
            float run = 0.f;
            const size_t base = (size_t)bh * NC_ * M_ + m;
            for (int c = 0; c < NC_; c++) {
                float* p = zc + base + (size_t)c * M_;
                const float t = *p; *p = run; run += t;
            }
        }
    }
}

// Pass C: per (bh, chunk): out = (Q S_pre + tril(Q K^T) V) / den
__global__ __launch_bounds__(256)
void passC_kernel(const float* __restrict__ qp, const float* __restrict__ kp,
                  const float* __restrict__ v, const float* __restrict__ Sc,
                  const float* __restrict__ zc, float* __restrict__ o) {
    extern __shared__ float sm[];
    float* qc  = sm;                        // SC_*KSTR_
    float* kc  = qc + SC_ * KSTR_;          // SC_*KSTR_ (reused for S_pre)
    float* vc  = kc + SC_ * KSTR_;          // SC_*DH_
    float* Am  = vc + SC_ * DH_;            // 64*65
    float* zp  = Am + 64 * 65;              // 272
    float* den = zp + 272;                  // 64

    const int bh = blockIdx.y, c = blockIdx.x;
    const int b = bh / H_, h = bh - b * H_;
    const int n0 = c * SC_;
    const int tid = threadIdx.x;
    const size_t fbase = (size_t)bh * N_ * M_;
    const size_t sbase = ((size_t)bh * NC_ + c) * (M_ * DH_);
    const size_t zbase = ((size_t)bh * NC_ + c) * M_;

    for (int i = tid; i < SC_ * KSTR_; i += 256) {
        int r = i / KSTR_, m = i - r * KSTR_;
        float qv = 0.f, kv = 0.f;
        if (m < M_) {
            const size_t gi = fbase + (size_t)(n0 + r) * M_ + m;
            qv = qp[gi]; kv = kp[gi];
        }
        qc[i] = qv; kc[i] = kv;
    }
    for (int i = tid; i < SC_ * DH_; i += 256) {
        int r = i >> 6, e = i & 63;
        vc[i] = v[((size_t)b * N_ + n0 + r) * D_ + h * DH_ + e];
    }
    for (int m = tid; m < 272; m += 256) zp[m] = (m < M_) ? zc[zbase + m] : 0.f;
    __syncthreads();

    const int tx = tid & 15, ty = tid >> 4;
    const int i0 = ty * 4;

    // Am[i][j] = q_i . k_j (full 64x64)
    {
        const int j0 = tx * 4;
        float acc[4][4] = {};
        for (int m = 0; m < M_; m++) {
            float qv[4], kv[4];
#pragma unroll
            for (int t = 0; t < 4; t++) qv[t] = qc[(i0 + t) * KSTR_ + m];
#pragma unroll
            for (int t = 0; t < 4; t++) kv[t] = kc[(j0 + t) * KSTR_ + m];
#pragma unroll
            for (int a = 0; a < 4; a++)
#pragma unroll
                for (int bb = 0; bb < 4; bb++) acc[a][bb] += qv[a] * kv[bb];
        }
#pragma unroll
        for (int a = 0; a < 4; a++)
#pragma unroll
            for (int bb = 0; bb < 4; bb++) Am[(i0 + a) * 65 + j0 + bb] = acc[a][bb];
    }
    __syncthreads();

    if (tid < SC_) {
        const float* qr = qc + tid * KSTR_;
        float s = 0.f, qs = 0.f;
        for (int m = 0; m < M_; m++) { const float qv = qr[m]; s += qv * zp[m]; qs += qv; }
        float acc = s + EPS_DEN_ * qs;
        for (int j = 0; j <= tid; j++) acc += Am[tid * 65 + j];
        den[tid] = acc;
    }
    __syncthreads();

    // overwrite kc with S_pre [m*64+e]
    for (int i = tid; i < M_ * DH_; i += 256) kc[i] = Sc[sbase + i];
    __syncthreads();

    // out
    {
        const int e0 = tx * 4;
        float acc[4][4] = {};
        for (int m = 0; m < M_; m++) {
            const float4 s4 = *(const float4*)&kc[m * DH_ + e0];
            float qv[4];
#pragma unroll
            for (int t = 0; t < 4; t++) qv[t] = qc[(i0 + t) * KSTR_ + m];
#pragma unroll
            for (int a = 0; a < 4; a++) {
                acc[a][0] += qv[a] * s4.x; acc[a][1] += qv[a] * s4.y;
                acc[a][2] += qv[a] * s4.z; acc[a][3] += qv[a] * s4.w;
            }
        }
        for (int j = 0; j < SC_; j++) {
            const float4 v4 = *(const float4*)&vc[j * DH_ + e0];
            float av[4];
#pragma unroll
            for (int t = 0; t < 4; t++) av[t] = (j <= i0 + t) ? Am[(i0 + t) * 65 + j] : 0.f;
#pragma unroll
            for (int a = 0; a < 4; a++) {
                acc[a][0] += av[a] * v4.x; acc[a][1] += av[a] * v4.y;
                acc[a][2] += av[a] * v4.z; acc[a][3] += av[a] * v4.w;
            }
        }
#pragma unroll
        for (int a = 0; a < 4; a++) {
            const int i = i0 + a;
            const float inv = 1.f / den[i];
            float4 r;
            r.x = acc[a][0] * inv; r.y = acc[a][1] * inv;
            r.z = acc[a][2] * inv; r.w = acc[a][3] * inv;
            *(float4*)&o[((size_t)b * N_ + n0 + i) * D_ + h * DH_ + e0] = r;
        }
    }
}

// ---------------- host launcher ----------------
extern "C" void kernel_launch(void* const* d_in, const int* in_sizes, int n_in,
                              void* d_out, int out_size) {
    const float* x     = (const float*)d_in[0];
    const float* ln1_g = (const float*)d_in[1];
    const float* ln1_b = (const float*)d_in[2];
    const float* Wq    = (const float*)d_in[3];
    const float* bq    = (const float*)d_in[4];
    const float* Wk    = (const float*)d_in[5];
    const float* bk    = (const float*)d_in[6];
    const float* Wv    = (const float*)d_in[7];
    const float* bv    = (const float*)d_in[8];
    const float* Wo    = (const float*)d_in[9];
    const float* bo    = (const float*)d_in[10];
    const float* proj  = (const float*)d_in[11];
    const float* ln2_g = (const float*)d_in[12];
    const float* ln2_b = (const float*)d_in[13];
    const float* W1    = (const float*)d_in[14];
    const float* b1    = (const float*)d_in[15];
    const float* W2    = (const float*)d_in[16];
    const float* b2    = (const float*)d_in[17];
    float* out = (float*)d_out;

    float *p_h, *p_q, *p_k, *p_v, *p_o, *p_x2, *p_qp, *p_kp, *p_ff, *p_Sc, *p_zc, *p_kmax;
    cudaGetSymbolAddress((void**)&p_h, g_h);
    cudaGetSymbolAddress((void**)&p_q, g_q);
    cudaGetSymbolAddress((void**)&p_k, g_k);
    cudaGetSymbolAddress((void**)&p_v, g_v);
    cudaGetSymbolAddress((void**)&p_o, g_o);
    cudaGetSymbolAddress((void**)&p_x2, g_x2);
    cudaGetSymbolAddress((void**)&p_qp, g_qp);
    cudaGetSymbolAddress((void**)&p_kp, g_kp);
    cudaGetSymbolAddress((void**)&p_ff, g_ff);
    cudaGetSymbolAddress((void**)&p_Sc, g_Sc);
    cudaGetSymbolAddress((void**)&p_zc, g_zc);
    cudaGetSymbolAddress((void**)&p_kmax, g_kmax);

    const int feat_smem  = (M_ * 65 + FROWS_ * DH_ + FROWS_ * M_) * 4;
    const int passA_smem = (SC_ * KSTR_ + SC_ * DH_) * 4;
    const int passC_smem = (2 * SC_ * KSTR_ + SC_ * DH_ + 64 * 65 + 272 + 64) * 4;
    cudaFuncSetAttribute(feat_kernel,  cudaFuncAttributeMaxDynamicSharedMemorySize, feat_smem);
    cudaFuncSetAttribute(passA_kernel, cudaFuncAttributeMaxDynamicSharedMemorySize, passA_smem);
    cudaFuncSetAttribute(passC_kernel, cudaFuncAttributeMaxDynamicSharedMemorySize, passC_smem);

    const int MR = B_ * N_;  // 4096 rows

    // 1. LN1
    ln_kernel<<<MR, 256>>>(x, ln1_g, ln1_b, p_h);

    // 2. QKV projections (tf32 TC)
    gemm_tc_kernel<<<dim3(D_ / 128, MR / 128), 256>>>(p_h, Wq, bq, nullptr, p_q, MR, D_, D_, 0);
    gemm_tc_kernel<<<dim3(D_ / 128, MR / 128), 256>>>(p_h, Wk, bk, nullptr, p_k, MR, D_, D_, 0);
    gemm_tc_kernel<<<dim3(D_ / 128, MR / 128), 256>>>(p_h, Wv, bv, nullptr, p_v, MR, D_, D_, 0);

    // 3. feature maps
    dim3 fgrid(N_ / FROWS_, H_, B_);
    feat_kernel<<<fgrid, 256, feat_smem>>>(p_q, proj, p_qp, nullptr, 1);
    kmax_init_kernel<<<1, 1>>>(p_kmax);
    feat_kernel<<<fgrid, 256, feat_smem>>>(p_k, proj, p_kp, p_kmax, 0);
    kexp_kernel<<<(BHNM_ + 255) / 256, 256>>>(p_kp, p_kmax);

    // 4. causal linear attention (3-pass parallel scan)
    passA_kernel<<<dim3(NC_, BH_), 256, passA_smem>>>(p_kp, p_v, p_Sc, p_zc);
    passB_kernel<<<dim3(BH_, 68), 256>>>(p_Sc, p_zc);
    passC_kernel<<<dim3(NC_, BH_), 256, passC_smem>>>(p_qp, p_kp, p_v, p_Sc, p_zc, p_o);

    // 5. output projection + residual
    gemm_tc_kernel<<<dim3(D_ / 128, MR / 128), 256>>>(p_o, Wo, bo, x, p_x2, MR, D_, D_, 0);

    // 6. LN2 + MLP
    ln_kernel<<<MR, 256>>>(p_x2, ln2_g, ln2_b, p_h);
    gemm_tc_kernel<<<dim3(FF_ / 128, MR / 128), 256>>>(p_h, W1, b1, nullptr, p_ff, MR, FF_, D_, 1);
    gemm_tc_kernel<<<dim3(D_ / 128, MR / 128), 256>>>(p_ff, W2, b2, p_x2, out, MR, D_, FF_, 0);
}

// round 3
// speedup vs baseline: 4.5409x; 1.2790x over previous
#include <cuda_runtime.h>
#include <math.h>

// ---------------- problem constants ----------------
constexpr int B_ = 2, N_ = 2048, D_ = 768, H_ = 12, DH_ = 64, M_ = 266, FF_ = 3072;
constexpr int QKV_N = 3 * D_;                    // 2304
constexpr int BND_  = B_ * N_ * D_;
constexpr int BHNM_ = B_ * H_ * N_ * M_;
constexpr int BNFF_ = B_ * N_ * FF_;
constexpr float DN_    = 0.35355339059327373f;   // 64^-0.25
constexpr float RATIO_ = 0.06131393283046181f;   // 266^-0.5
constexpr float EPS_KER_ = 1e-4f;
constexpr float EPS_DEN_ = 1e-6f;

constexpr int SC_ = 64;          // scan chunk
constexpr int NC_ = N_ / SC_;    // 32 chunks
constexpr int BH_ = B_ * H_;     // 24
constexpr int KSTR_ = 273;       // padded feature stride

// ---------------- scratch (device globals; no allocation allowed) -----------
__device__ float g_h  [BND_];
__device__ float g_qkv[(size_t)B_ * N_ * QKV_N];
__device__ float g_o  [BND_];
__device__ float g_x2 [BND_];
__device__ float g_qp [BHNM_];
__device__ float g_kp [BHNM_];
__device__ float g_ff [BNFF_];
__device__ float g_Sc [(size_t)BH_ * NC_ * (M_ * DH_)];
__device__ float g_zc [(size_t)BH_ * NC_ * M_];
__device__ float g_Wqkv[(size_t)D_ * QKV_N];
__device__ float g_bqkv[QKV_N];
__device__ float g_kmax[1];

// ---------------- helpers ----------------
__device__ __forceinline__ void atomicMaxFloat(float* addr, float val) {
    int* ia = (int*)addr;
    int old = *ia;
    while (__int_as_float(old) < val) {
        int assumed = old;
        old = atomicCAS(ia, assumed, __float_as_int(val));
        if (old == assumed) break;
    }
}

__device__ __forceinline__ float gelu_exact(float v) {
    return 0.5f * v * (1.0f + erff(v * 0.70710678118654752f));
}

__device__ __forceinline__ void cpasync16(float* smem, const float* gmem) {
    unsigned s = (unsigned)__cvta_generic_to_shared(smem);
    asm volatile("cp.async.cg.shared.global [%0], [%1], 16;\n" :: "r"(s), "l"(gmem));
}
__device__ __forceinline__ void cp_commit() { asm volatile("cp.async.commit_group;\n"); }
template <int NN>
__device__ __forceinline__ void cp_wait() { asm volatile("cp.async.wait_group %0;\n" :: "n"(NN)); }

// ---------------- pack QKV weights/biases into fused buffers ----------------
__global__ void pack_qkv_kernel(const float* __restrict__ Wq, const float* __restrict__ Wk,
                                const float* __restrict__ Wv, const float* __restrict__ bq,
                                const float* __restrict__ bk, const float* __restrict__ bv,
                                float* __restrict__ W, float* __restrict__ bvec) {
    const int i = blockIdx.x * 256 + threadIdx.x;
    if (i < 3 * D_ * D_) {
        const int which = i / (D_ * D_);
        const int rem = i - which * (D_ * D_);
        const int r = rem / D_, c = rem - r * D_;
        const float* src = (which == 0) ? Wq : (which == 1) ? Wk : Wv;
        W[(size_t)r * QKV_N + which * D_ + c] = src[rem];
        if (r == 0) {
            const float* bs = (which == 0) ? bq : (which == 1) ? bk : bv;
            bvec[which * D_ + c] = bs[c];
        }
    }
}

// ---------------- layernorm ----------------
__global__ void ln_kernel(const float* __restrict__ x, const float* __restrict__ g,
                          const float* __restrict__ b, float* __restrict__ y) {
    __shared__ float red[256];
    const int row = blockIdx.x;
    const int tid = threadIdx.x;
    const float* xr = x + (size_t)row * D_;

    float s = 0.f;
    for (int i = tid; i < D_; i += 256) s += xr[i];
    red[tid] = s; __syncthreads();
    for (int o = 128; o > 0; o >>= 1) { if (tid < o) red[tid] += red[tid + o]; __syncthreads(); }
    const float mu = red[0] * (1.0f / D_);
    __syncthreads();

    float s2 = 0.f;
    for (int i = tid; i < D_; i += 256) { float d = xr[i] - mu; s2 += d * d; }
    red[tid] = s2; __syncthreads();
    for (int o = 128; o > 0; o >>= 1) { if (tid < o) red[tid] += red[tid + o]; __syncthreads(); }
    const float inv = rsqrtf(red[0] * (1.0f / D_) + 1e-5f);

    float* yr = y + (size_t)row * D_;
    for (int i = tid; i < D_; i += 256) yr[i] = (xr[i] - mu) * inv * g[i] + b[i];
}

// ---------------- tf32 TC GEMM, cp.async double-buffered ----------------
// C[Md,Nd] = act(A[Md,Kd] @ Bm[Kd,Nd] + bias)(+resid). Md%128==0, Nd%128==0, Kd%32==0.
constexpr int ASTR = 36;    // floats (32+4)
constexpr int BSTR = 136;   // floats (128+8)
constexpr int ATILE = 128 * ASTR;
constexpr int BTILE = 32 * BSTR;
constexpr int GEMM_SMEM = (2 * ATILE + 2 * BTILE) * 4;   // 71680 B

__global__ __launch_bounds__(256)
void gemm_tc_kernel(const float* __restrict__ A, const float* __restrict__ Bm,
                    const float* __restrict__ bias, const float* __restrict__ resid,
                    float* __restrict__ C, int Md, int Nd, int Kd, int act) {
    extern __shared__ float sm[];
    float* As = sm;               // 2 stages
    float* Bs = sm + 2 * ATILE;   // 2 stages

    const int tid = threadIdx.x;
    const int lane = tid & 31, warp = tid >> 5;
    const int warp_m = warp >> 2, warp_n = warp & 3;
    const int g = lane >> 2, tg = lane & 3;
    const int row0 = blockIdx.y * 128, col0 = blockIdx.x * 128;

    // load indices (16B chunks)
    const int a_r = tid >> 1;                // with p-loop below: rows tid>>1 (128 rows, 2 chunks each? see below)
    // A tile: 128 rows x 8 chunks = 1024; thread handles 4: idx = tid + p*256
    // B tile: 32 rows x 32 chunks = 1024; same scheme
    float c[4][4][4];
#pragma unroll
    for (int mt = 0; mt < 4; mt++)
#pragma unroll
        for (int nt = 0; nt < 4; nt++)
#pragma unroll
            for (int u = 0; u < 4; u++) c[mt][nt][u] = 0.f;

    const int ntiles = Kd >> 5;

    auto prefetch = [&](int t, int stage) {
        const int k0 = t << 5;
        float* as = As + stage * ATILE;
        float* bs = Bs + stage * BTILE;
#pragma unroll
        for (int p = 0; p < 4; p++) {
            const int idx = tid + p * 256;
            const int r = idx >> 3, c4 = (idx & 7) << 2;
            cpasync16(&as[r * ASTR + c4], &A[(size_t)(row0 + r) * Kd + k0 + c4]);
        }
#pragma unroll
        for (int p = 0; p < 4; p++) {
            const int idx = tid + p * 256;
            const int r = idx >> 5, c4 = (idx & 31) << 2;
            cpasync16(&bs[r * BSTR + c4], &Bm[(size_t)(k0 + r) * Nd + col0 + c4]);
        }
        cp_commit();
    };

    prefetch(0, 0);

    for (int t = 0; t < ntiles; t++) {
        if (t + 1 < ntiles) { prefetch(t + 1, (t + 1) & 1); cp_wait<1>(); }
        else cp_wait<0>();
        __syncthreads();

        const float* as = As + (t & 1) * ATILE;
        const float* bs = Bs + (t & 1) * BTILE;
#pragma unroll
        for (int k8 = 0; k8 < 4; k8++) {
            const int kk = k8 * 8;
            unsigned af[4][4], bf[4][2];
#pragma unroll
            for (int mt = 0; mt < 4; mt++) {
                const int rb = warp_m * 64 + mt * 16;
                af[mt][0] = __float_as_uint(as[(rb + g)     * ASTR + kk + tg]);
                af[mt][1] = __float_as_uint(as[(rb + g + 8) * ASTR + kk + tg]);
                af[mt][2] = __float_as_uint(as[(rb + g)     * ASTR + kk + tg + 4]);
                af[mt][3] = __float_as_uint(as[(rb + g + 8) * ASTR + kk + tg + 4]);
            }
#pragma unroll
            for (int nt = 0; nt < 4; nt++) {
                const int cb = warp_n * 32 + nt * 8 + g;
                bf[nt][0] = __float_as_uint(bs[(kk + tg)     * BSTR + cb]);
                bf[nt][1] = __float_as_uint(bs[(kk + tg + 4) * BSTR + cb]);
            }
#pragma unroll
            for (int mt = 0; mt < 4; mt++)
#pragma unroll
                for (int nt = 0; nt < 4; nt++) {
                    asm volatile(
                        "mma.sync.aligned.m16n8k8.row.col.f32.tf32.tf32.f32 "
                        "{%0,%1,%2,%3}, {%4,%5,%6,%7}, {%8,%9}, {%0,%1,%2,%3};"
                        : "+f"(c[mt][nt][0]), "+f"(c[mt][nt][1]),
                          "+f"(c[mt][nt][2]), "+f"(c[mt][nt][3])
                        : "r"(af[mt][0]), "r"(af[mt][1]), "r"(af[mt][2]), "r"(af[mt][3]),
                          "r"(bf[nt][0]), "r"(bf[nt][1]));
                }
        }
        __syncthreads();
    }

    // epilogue
#pragma unroll
    for (int mt = 0; mt < 4; mt++) {
        const int r1 = row0 + warp_m * 64 + mt * 16 + g;
        const int r2 = r1 + 8;
#pragma unroll
        for (int nt = 0; nt < 4; nt++) {
            const int cc = col0 + warp_n * 32 + nt * 8 + 2 * tg;
            const float b0 = bias[cc], b1 = bias[cc + 1];
            float v00 = c[mt][nt][0] + b0, v01 = c[mt][nt][1] + b1;
            float v10 = c[mt][nt][2] + b0, v11 = c[mt][nt][3] + b1;
            if (act == 1) {
                v00 = gelu_exact(v00); v01 = gelu_exact(v01);
                v10 = gelu_exact(v10); v11 = gelu_exact(v11);
            }
            if (resid) {
                const float2 q0 = *(const float2*)&resid[(size_t)r1 * Nd + cc];
                const float2 q1 = *(const float2*)&resid[(size_t)r2 * Nd + cc];
                v00 += q0.x; v01 += q0.y; v10 += q1.x; v11 += q1.y;
            }
            *(float2*)&C[(size_t)r1 * Nd + cc] = make_float2(v00, v01);
            *(float2*)&C[(size_t)r2 * Nd + cc] = make_float2(v10, v11);
        }
    }
}

// ---------------- FAVOR+ feature kernel ----------------
constexpr int FROWS_ = 16;

__global__ void feat_kernel(const float* __restrict__ data,  // rows stride ld, head h at col h*DH
                            int ld,
                            const float* __restrict__ proj,  // [M,DH]
                            float* __restrict__ outp,        // [B,H,N,M]
                            float* __restrict__ kmax, int is_query) {
    extern __shared__ float sm[];
    float* sproj = sm;                       // M_ * 65
    float* srow  = sproj + M_ * 65;          // FROWS_ * DH_
    float* sdd   = srow + FROWS_ * DH_;      // FROWS_ * M_
    __shared__ float sdiag[FROWS_];
    __shared__ float smx[FROWS_];
    __shared__ float red[256];

    const int b = blockIdx.z, h = blockIdx.y, n0 = blockIdx.x * FROWS_;
    const int tid = threadIdx.x;

    for (int i = tid; i < M_ * DH_; i += 256) {
        int m = i / DH_, d = i - m * DH_;
        sproj[m * 65 + d] = proj[i];
    }
    for (int i = tid; i < FROWS_ * DH_; i += 256) {
        int r = i >> 6, d = i & 63;
        srow[i] = data[((size_t)b * N_ + n0 + r) * ld + h * DH_ + d];
    }
    __syncthreads();

    for (int i = tid; i < FROWS_ * M_; i += 256) {
        int r = i / M_, m = i - r * M_;
        const float* dp = srow + r * DH_;
        const float* pp = sproj + m * 65;
        float acc = 0.f;
#pragma unroll
        for (int d = 0; d < DH_; d++) acc += dp[d] * pp[d];
        sdd[i] = acc * DN_;
    }
    __syncthreads();

    if (tid < FROWS_) {
        const float* dp = srow + tid * DH_;
        float s = 0.f;
#pragma unroll
        for (int d = 0; d < DH_; d++) s += dp[d] * dp[d];
        sdiag[tid] = s * 0.5f * DN_ * DN_;
        if (is_query) {
            float mx = -3e38f;
            for (int m = 0; m < M_; m++) mx = fmaxf(mx, sdd[tid * M_ + m]);
            smx[tid] = mx;
        }
    }
    __syncthreads();

    const size_t obase = ((size_t)(b * H_ + h) * N_ + n0) * M_;
    if (is_query) {
        for (int i = tid; i < FROWS_ * M_; i += 256) {
            int r = i / M_, m = i - r * M_;
            outp[obase + (size_t)r * M_ + m] =
                RATIO_ * (expf(sdd[i] - sdiag[r] - smx[r]) + EPS_KER_);
        }
    } else {
        float lmax = -3e38f;
        for (int i = tid; i < FROWS_ * M_; i += 256) {
            int r = i / M_, m = i - r * M_;
            float v = sdd[i];
            lmax = fmaxf(lmax, v);
            outp[obase + (size_t)r * M_ + m] = v - sdiag[r];
        }
        red[tid] = lmax; __syncthreads();
        for (int o = 128; o > 0; o >>= 1) { if (tid < o) red[tid] = fmaxf(red[tid], red[tid + o]); __syncthreads(); }
        if (tid == 0) atomicMaxFloat(kmax, red[0]);
    }
}

__global__ void kmax_init_kernel(float* kmax) { kmax[0] = -3e38f; }

// ---------------- causal linear attention: 3-pass parallel scan ----------------
// kp holds RAW (dd - diag); exp applied on load using kmax.
__device__ __forceinline__ float kfinal(float v, float km) {
    return RATIO_ * (expf(v - km) + EPS_KER_);
}

__global__ void passA_kernel(const float* __restrict__ kp, const float* __restrict__ kmaxp,
                             const float* __restrict__ v, int ld,
                             float* __restrict__ Sc, float* __restrict__ zc) {
    extern __shared__ float sm[];
    float* kc = sm;                   // SC_*KSTR_
    float* vc = kc + SC_ * KSTR_;     // SC_*DH_
    const int bh = blockIdx.y, c = blockIdx.x;
    const int b = bh / H_, h = bh - b * H_;
    const int n0 = c * SC_;
    const int tid = threadIdx.x;
    const size_t fbase = (size_t)bh * N_ * M_;
    const float km = *kmaxp;

    for (int i = tid; i < SC_ * KSTR_; i += 256) {
        int r = i / KSTR_, m = i - r * KSTR_;
        kc[i] = (m < M_) ? kfinal(kp[fbase + (size_t)(n0 + r) * M_ + m], km) : 0.f;
    }
    for (int i = tid; i < SC_ * DH_; i += 256) {
        int r = i >> 6, e = i & 63;
        vc[i] = v[((size_t)b * N_ + n0 + r) * ld + h * DH_ + e];
    }
    __syncthreads();

    const int e = tid & 63;
    const int mg = tid >> 6;
    float* out = Sc + ((size_t)bh * NC_ + c) * (M_ * DH_);
    for (int m0 = mg * 8; m0 < 272; m0 += 32) {
        float acc[8] = {};
        for (int j = 0; j < SC_; j++) {
            const float vv = vc[j * DH_ + e];
#pragma unroll
            for (int t = 0; t < 8; t++) acc[t] += kc[j * KSTR_ + m0 + t] * vv;
        }
#pragma unroll
        for (int t = 0; t < 8; t++)
            if (m0 + t < M_) out[(m0 + t) * DH_ + e] = acc[t];
    }
    for (int m = tid; m < M_; m += 256) {
        float s = 0.f;
        for (int j = 0; j < SC_; j++) s += kc[j * KSTR_ + m];
        zc[((size_t)bh * NC_ + c) * M_ + m] = s;
    }
}

__global__ void passB_kernel(float* __restrict__ Sc, float* __restrict__ zc) {
    const int bh = blockIdx.x;
    const int i = blockIdx.y * 256 + threadIdx.x;
    if (i < M_ * DH_) {
        float run = 0.f;
        const size_t base = (size_t)bh * NC_ * (M_ * DH_) + i;
        for (int c = 0; c < NC_; c++) {
            float* p = Sc + base + (size_t)c * (M_ * DH_);
            const float t = *p; *p = run; run += t;
        }
    } else {
        const int m = i - M_ * DH_;
        if (m < M_) {
            float run = 0.f;
            const size_t base = (size_t)bh * NC_ * M_ + m;
            for (int c = 0; c < NC_; c++) {
                float* p = zc + base + (size_t)c * M_;
                const float t = *p; *p = run; run += t;
            }
        }
    }
}

__global__ __launch_bounds__(256)
void passC_kernel(const float* __restrict__ qp, const float* __restrict__ kp,
                  const float* __restrict__ kmaxp,
                  const float* __restrict__ v, int ld,
                  const float* __restrict__ Sc, const float* __restrict__ zc,
                  float* __restrict__ o) {
    extern __shared__ float sm[];
    float* qc  = sm;                        // SC_*KSTR_
    float* kc  = qc + SC_ * KSTR_;          // SC_*KSTR_ (reused for S_pre)
    float* vc  = kc + SC_ * KSTR_;          // SC_*DH_
    float* Am  = vc + SC_ * DH_;            // 64*65
    float* zp  = Am + 64 * 65;              // 272
    float* den = zp + 272;                  // 64

    const int bh = blockIdx.y, c = blockIdx.x;
    const int b = bh / H_, h = bh - b * H_;
    const int n0 = c * SC_;
    const int tid = threadIdx.x;
    const size_t fbase = (size_t)bh * N_ * M_;
    const size_t sbase = ((size_t)bh * NC_ + c) * (M_ * DH_);
    const size_t zbase = ((size_t)bh * NC_ + c) * M_;
    const float km = *kmaxp;

    for (int i = tid; i < SC_ * KSTR_; i += 256) {
        int r = i / KSTR_, m = i - r * KSTR_;
        float qv = 0.f, kv = 0.f;
        if (m < M_) {
            const size_t gi = fbase + (size_t)(n0 + r) * M_ + m;
            qv = qp[gi]; kv = kfinal(kp[gi], km);
        }
        qc[i] = qv; kc[i] = kv;
    }
    for (int i = tid; i < SC_ * DH_; i += 256) {
        int r = i >> 6, e = i & 63;
        vc[i] = v[((size_t)b * N_ + n0 + r) * ld + h * DH_ + e];
    }
    for (int m = tid; m < 272; m += 256) zp[m] = (m < M_) ? zc[zbase + m] : 0.f;
    __syncthreads();

    const int tx = tid & 15, ty = tid >> 4;
    const int i0 = ty * 4;

    {
        const int j0 = tx * 4;
        float acc[4][4] = {};
        for (int m = 0; m < M_; m++) {
            float qv[4], kv[4];
#pragma unroll
            for (int t = 0; t < 4; t++) qv[t] = qc[(i0 + t) * KSTR_ + m];
#pragma unroll
            for (int t = 0; t < 4; t++) kv[t] = kc[(j0 + t) * KSTR_ + m];
#pragma unroll
            for (int a = 0; a < 4; a++)
#pragma unroll
                for (int bb = 0; bb < 4; bb++) acc[a][bb] += qv[a] * kv[bb];
        }
#pragma unroll
        for (int a = 0; a < 4; a++)
#pragma unroll
            for (int bb = 0; bb < 4; bb++) Am[(i0 + a) * 65 + j0 + bb] = acc[a][bb];
    }
    __syncthreads();

    if (tid < SC_) {
        const float* qr = qc + tid * KSTR_;
        float s = 0.f, qs = 0.f;
        for (int m = 0; m < M_; m++) { const float qv = qr[m]; s += qv * zp[m]; qs += qv; }
        float acc = s + EPS_DEN_ * qs;
        for (int j = 0; j <= tid; j++) acc += Am[tid * 65 + j];
        den[tid] = acc;
    }
    __syncthreads();

    for (int i = tid; i < M_ * DH_; i += 256) kc[i] = Sc[sbase + i];
    __syncthreads();

    {
        const int e0 = tx * 4;
        float acc[4][4] = {};
        for (int m = 0; m < M_; m++) {
            const float4 s4 = *(const float4*)&kc[m * DH_ + e0];
            float qv[4];
#pragma unroll
            for (int t = 0; t < 4; t++) qv[t] = qc[(i0 + t) * KSTR_ + m];
#pragma unroll
            for (int a = 0; a < 4; a++) {
                acc[a][0] += qv[a] * s4.x; acc[a][1] += qv[a] * s4.y;
                acc[a][2] += qv[a] * s4.z; acc[a][3] += qv[a] * s4.w;
            }
        }
        for (int j = 0; j < SC_; j++) {
            const float4 v4 = *(const float4*)&vc[j * DH_ + e0];
            float av[4];
#pragma unroll
            for (int t = 0; t < 4; t++) av[t] = (j <= i0 + t) ? Am[(i0 + t) * 65 + j] : 0.f;
#pragma unroll
            for (int a = 0; a < 4; a++) {
                acc[a][0] += av[a] * v4.x; acc[a][1] += av[a] * v4.y;
                acc[a][2] += av[a] * v4.z; acc[a][3] += av[a] * v4.w;
            }
        }
#pragma unroll
        for (int a = 0; a < 4; a++) {
            const int i = i0 + a;
            const float inv = 1.f / den[i];
            float4 r;
            r.x = acc[a][0] * inv; r.y = acc[a][1] * inv;
            r.z = acc[a][2] * inv; r.w = acc[a][3] * inv;
            *(float4*)&o[((size_t)b * N_ + n0 + i) * D_ + h * DH_ + e0] = r;
        }
    }
}

// ---------------- host launcher ----------------
extern "C" void kernel_launch(void* const* d_in, const int* in_sizes, int n_in,
                              void* d_out, int out_size) {
    const float* x     = (const float*)d_in[0];
    const float* ln1_g = (const float*)d_in[1];
    const float* ln1_b = (const float*)d_in[2];
    const float* Wq    = (const float*)d_in[3];
    const float* bq    = (const float*)d_in[4];
    const float* Wk    = (const float*)d_in[5];
    const float* bk    = (const float*)d_in[6];
    const float* Wv    = (const float*)d_in[7];
    const float* bv    = (const float*)d_in[8];
    const float* Wo    = (const float*)d_in[9];
    const float* bo    = (const float*)d_in[10];
    const float* proj  = (const float*)d_in[11];
    const float* ln2_g = (const float*)d_in[12];
    const float* ln2_b = (const float*)d_in[13];
    const float* W1    = (const float*)d_in[14];
    const float* b1    = (const float*)d_in[15];
    const float* W2    = (const float*)d_in[16];
    const float* b2    = (const float*)d_in[17];
    float* out = (float*)d_out;

    float *p_h, *p_qkv, *p_o, *p_x2, *p_qp, *p_kp, *p_ff, *p_Sc, *p_zc, *p_W, *p_b, *p_kmax;
    cudaGetSymbolAddress((void**)&p_h, g_h);
    cudaGetSymbolAddress((void**)&p_qkv, g_qkv);
    cudaGetSymbolAddress((void**)&p_o, g_o);
    cudaGetSymbolAddress((void**)&p_x2, g_x2);
    cudaGetSymbolAddress((void**)&p_qp, g_qp);
    cudaGetSymbolAddress((void**)&p_kp, g_kp);
    cudaGetSymbolAddress((void**)&p_ff, g_ff);
    cudaGetSymbolAddress((void**)&p_Sc, g_Sc);
    cudaGetSymbolAddress((void**)&p_zc, g_zc);
    cudaGetSymbolAddress((void**)&p_W, g_Wqkv);
    cudaGetSymbolAddress((void**)&p_b, g_bqkv);
    cudaGetSymbolAddress((void**)&p_kmax, g_kmax);

    const int feat_smem  = (M_ * 65 + FROWS_ * DH_ + FROWS_ * M_) * 4;
    const int passA_smem = (SC_ * KSTR_ + SC_ * DH_) * 4;
    const int passC_smem = (2 * SC_ * KSTR_ + SC_ * DH_ + 64 * 65 + 272 + 64) * 4;
    cudaFuncSetAttribute(gemm_tc_kernel, cudaFuncAttributeMaxDynamicSharedMemorySize, GEMM_SMEM);
    cudaFuncSetAttribute(feat_kernel,  cudaFuncAttributeMaxDynamicSharedMemorySize, feat_smem);
    cudaFuncSetAttribute(passA_kernel, cudaFuncAttributeMaxDynamicSharedMemorySize, passA_smem);
    cudaFuncSetAttribute(passC_kernel, cudaFuncAttributeMaxDynamicSharedMemorySize, passC_smem);

    const int MR = B_ * N_;  // 4096

    // 0. pack fused QKV weights
    pack_qkv_kernel<<<(3 * D_ * D_ + 255) / 256, 256>>>(Wq, Wk, Wv, bq, bk, bv, p_W, p_b);

    // 1. LN1
    ln_kernel<<<MR, 256>>>(x, ln1_g, ln1_b, p_h);

    // 2. fused QKV projection
    gemm_tc_kernel<<<dim3(QKV_N / 128, MR / 128), 256, GEMM_SMEM>>>(
        p_h, p_W, p_b, nullptr, p_qkv, MR, QKV_N, D_, 0);

    // 3. feature maps (q final; k raw dd-diag + global max)
    dim3 fgrid(N_ / FROWS_, H_, B_);
    feat_kernel<<<fgrid, 256, feat_smem>>>(p_qkv + 0,  QKV_N, proj, p_qp, nullptr, 1);
    kmax_init_kernel<<<1, 1>>>(p_kmax);
    feat_kernel<<<fgrid, 256, feat_smem>>>(p_qkv + D_, QKV_N, proj, p_kp, p_kmax, 0);

    // 4. causal linear attention (exp fused into passA/passC loads)
    passA_kernel<<<dim3(NC_, BH_), 256, passA_smem>>>(p_kp, p_kmax, p_qkv + 2 * D_, QKV_N, p_Sc, p_zc);
    passB_kernel<<<dim3(BH_, 68), 256>>>(p_Sc, p_zc);
    passC_kernel<<<dim3(NC_, BH_), 256, passC_smem>>>(p_qp, p_kp, p_kmax, p_qkv + 2 * D_, QKV_N,
                                                      p_Sc, p_zc, p_o);

    // 5. output projection + residual
    gemm_tc_kernel<<<dim3(D_ / 128, MR / 128), 256, GEMM_SMEM>>>(
        p_o, Wo, bo, x, p_x2, MR, D_, D_, 0);

    // 6. LN2 + MLP
    ln_kernel<<<MR, 256>>>(p_x2, ln2_g, ln2_b, p_h);
    gemm_tc_kernel<<<dim3(FF_ / 128, MR / 128), 256, GEMM_SMEM>>>(
        p_h, W1, b1, nullptr, p_ff, MR, FF_, D_, 1);
    gemm_tc_kernel<<<dim3(D_ / 128, MR / 128), 256, GEMM_SMEM>>>(
        p_ff, W2, b2, p_x2, out, MR, D_, FF_, 0);
}